// round 1
// baseline (speedup 1.0000x reference)
#include <cuda_runtime.h>
#include <math.h>

// Problem constants
#define BATCH   16384
#define TSTEPS  28
#define FEAT    28
#define HID     128
#define G3      384     // 3*HID
#define NCLS    10

#define TILE_B  64
#define NTHREADS 512
#define KC      16      // R streaming chunk (rows of k)

// SMEM layout (floats):
//   h_s : [HID][TILE_B]          = 8192
//   W_s : [FEAT][G3]             = 10752
//   x_s : [FEAT][TILE_B]         = 1792
//   R_s : [KC][G3]               = 6144
#define SM_FLOATS (HID*TILE_B + FEAT*G3 + FEAT*TILE_B + KC*G3)
#define SM_BYTES  (SM_FLOATS * 4)

__device__ __forceinline__ float sigmoidf_(float v) {
    return 1.0f / (1.0f + __expf(-v));
}

__global__ __launch_bounds__(NTHREADS, 1)
void gru_fused_kernel(const float* __restrict__ x,      // (B,T,F,1)
                      const float* __restrict__ Wk,     // (F,3H)
                      const float* __restrict__ Rk,     // (H,3H)
                      const float* __restrict__ bias,   // (2,3H)
                      const float* __restrict__ dw,     // (H,C)
                      const float* __restrict__ db,     // (C)
                      float* __restrict__ out)          // (B,C)
{
    extern __shared__ float sm[];
    float* h_s = sm;                          // h_s[j*TILE_B + row], j = hidden col
    float* W_s = h_s + HID * TILE_B;          // W_s[k*G3 + c]
    float* x_s = W_s + FEAT * G3;             // x_s[f*TILE_B + row]
    float* R_s = x_s + FEAT * TILE_B;         // R_s[kk*G3 + c]

    const int tid = threadIdx.x;
    const int rg  = tid & 15;                 // 16 row groups * 4 rows = 64 rows
    const int cg  = tid >> 4;                 // 32 col groups * 4 cols = 128 h-cols
    const int r0  = rg * 4;
    const int j0  = cg * 4;
    const int b0  = blockIdx.x * TILE_B;

    // Load input-kernel W into SMEM (reused all 28 steps)
    for (int i = tid; i < FEAT * G3; i += NTHREADS) W_s[i] = Wk[i];
    // h0 = 0
    for (int i = tid; i < HID * TILE_B; i += NTHREADS) h_s[i] = 0.0f;

    // Per-thread gate biases (bias_i = bias[0..383], bias_r = bias[384..767])
    float bz[4], brg[4], bxh[4], brh[4];
#pragma unroll
    for (int c = 0; c < 4; c++) {
        bz[c]  = bias[j0 + c]            + bias[G3 + j0 + c];
        brg[c] = bias[HID + j0 + c]      + bias[G3 + HID + j0 + c];
        bxh[c] = bias[2*HID + j0 + c];
        brh[c] = bias[G3 + 2*HID + j0 + c];
    }

    __syncthreads();

    for (int t = 0; t < TSTEPS; t++) {
        // Stage x tile (transposed): x_s[f][row] = x[b0+row][t][f]
        for (int i = tid; i < FEAT * TILE_B; i += NTHREADS) {
            int row = i / FEAT;
            int f   = i % FEAT;
            x_s[f * TILE_B + row] =
                x[(size_t)(b0 + row) * (TSTEPS * FEAT) + t * FEAT + f];
        }
        __syncthreads();   // x_s ready; also orders prev-step h writes before h reads

        // Accumulators: z (x+rec fused), r (fused), rec-h, x-h
        float az[4][4], ar[4][4], ah[4][4], axh[4][4];
#pragma unroll
        for (int rr = 0; rr < 4; rr++)
#pragma unroll
            for (int c = 0; c < 4; c++) {
                az[rr][c] = 0.f; ar[rr][c] = 0.f;
                ah[rr][c] = 0.f; axh[rr][c] = 0.f;
            }

        // ---- Input projection: K = 28 over (x_s, W_s) ----
#pragma unroll 4
        for (int k = 0; k < FEAT; k++) {
            float4 a  = *(const float4*)&x_s[k * TILE_B + r0];
            float4 v0 = *(const float4*)&W_s[k * G3 + j0];
            float4 v1 = *(const float4*)&W_s[k * G3 + HID + j0];
            float4 v2 = *(const float4*)&W_s[k * G3 + 2*HID + j0];
            float av[4] = {a.x, a.y, a.z, a.w};
            float v0v[4] = {v0.x, v0.y, v0.z, v0.w};
            float v1v[4] = {v1.x, v1.y, v1.z, v1.w};
            float v2v[4] = {v2.x, v2.y, v2.z, v2.w};
#pragma unroll
            for (int rr = 0; rr < 4; rr++)
#pragma unroll
                for (int c = 0; c < 4; c++) {
                    az[rr][c]  = fmaf(av[rr], v0v[c], az[rr][c]);
                    ar[rr][c]  = fmaf(av[rr], v1v[c], ar[rr][c]);
                    axh[rr][c] = fmaf(av[rr], v2v[c], axh[rr][c]);
                }
        }

        // ---- Recurrent projection: K = 128 over (h_s, R streamed) ----
        for (int ch = 0; ch < HID / KC; ch++) {
            __syncthreads();   // previous chunk's compute done before R_s overwrite
            for (int i = tid; i < KC * G3; i += NTHREADS)
                R_s[i] = Rk[ch * KC * G3 + i];
            __syncthreads();
#pragma unroll 4
            for (int kk = 0; kk < KC; kk++) {
                int k = ch * KC + kk;
                float4 a  = *(const float4*)&h_s[k * TILE_B + r0];
                float4 v0 = *(const float4*)&R_s[kk * G3 + j0];
                float4 v1 = *(const float4*)&R_s[kk * G3 + HID + j0];
                float4 v2 = *(const float4*)&R_s[kk * G3 + 2*HID + j0];
                float av[4] = {a.x, a.y, a.z, a.w};
                float v0v[4] = {v0.x, v0.y, v0.z, v0.w};
                float v1v[4] = {v1.x, v1.y, v1.z, v1.w};
                float v2v[4] = {v2.x, v2.y, v2.z, v2.w};
#pragma unroll
                for (int rr = 0; rr < 4; rr++)
#pragma unroll
                    for (int c = 0; c < 4; c++) {
                        az[rr][c] = fmaf(av[rr], v0v[c], az[rr][c]);
                        ar[rr][c] = fmaf(av[rr], v1v[c], ar[rr][c]);
                        ah[rr][c] = fmaf(av[rr], v2v[c], ah[rr][c]);
                    }
            }
        }

        // ---- Gates + state update ----
        float hn[4][4];
#pragma unroll
        for (int c = 0; c < 4; c++) {
            float4 hv = *(const float4*)&h_s[(j0 + c) * TILE_B + r0];
            float ho[4] = {hv.x, hv.y, hv.z, hv.w};
#pragma unroll
            for (int rr = 0; rr < 4; rr++) {
                float z  = sigmoidf_(az[rr][c] + bz[c]);
                float r  = sigmoidf_(ar[rr][c] + brg[c]);
                float hh = tanhf(axh[rr][c] + bxh[c] + r * (ah[rr][c] + brh[c]));
                hn[rr][c] = z * ho[rr] + (1.0f - z) * hh;
            }
        }

        __syncthreads();   // all h_s reads complete before overwrite
#pragma unroll
        for (int c = 0; c < 4; c++) {
            float4 v = make_float4(hn[0][c], hn[1][c], hn[2][c], hn[3][c]);
            *(float4*)&h_s[(j0 + c) * TILE_B + r0] = v;
        }
        // next iteration's x-ready sync orders these writes before the next reads
    }

    __syncthreads();

    // ---- Dense + softmax epilogue (h resident in SMEM) ----
    if (tid < TILE_B) {
        const int row = tid;
        float lg[NCLS];
#pragma unroll
        for (int c = 0; c < NCLS; c++) lg[c] = db[c];
        for (int j = 0; j < HID; j++) {
            float hv = h_s[j * TILE_B + row];
#pragma unroll
            for (int c = 0; c < NCLS; c++)
                lg[c] = fmaf(hv, dw[j * NCLS + c], lg[c]);
        }
        float m = lg[0];
#pragma unroll
        for (int c = 1; c < NCLS; c++) m = fmaxf(m, lg[c]);
        float s = 0.0f;
#pragma unroll
        for (int c = 0; c < NCLS; c++) { lg[c] = expf(lg[c] - m); s += lg[c]; }
        float inv = 1.0f / s;
#pragma unroll
        for (int c = 0; c < NCLS; c++)
            out[(size_t)(b0 + row) * NCLS + c] = lg[c] * inv;
    }
}

extern "C" void kernel_launch(void* const* d_in, const int* in_sizes, int n_in,
                              void* d_out, int out_size) {
    const float* x    = (const float*)d_in[0];
    const float* Wk   = (const float*)d_in[1];
    const float* Rk   = (const float*)d_in[2];
    const float* bias = (const float*)d_in[3];
    const float* dw   = (const float*)d_in[4];
    const float* db   = (const float*)d_in[5];
    float* out = (float*)d_out;

    cudaFuncSetAttribute(gru_fused_kernel,
                         cudaFuncAttributeMaxDynamicSharedMemorySize, SM_BYTES);

    gru_fused_kernel<<<BATCH / TILE_B, NTHREADS, SM_BYTES>>>(
        x, Wk, Rk, bias, dw, db, out);
}

// round 2
// speedup vs baseline: 1.0012x; 1.0012x over previous
#include <cuda_runtime.h>
#include <math.h>

// Problem constants
#define BATCH   16384
#define TSTEPS  28
#define FEAT    28
#define HID     128
#define G3      384     // 3*HID
#define NCLS    10

#define TILE_B  64
#define NTHREADS 512
#define KC      16      // R streaming chunk (rows of k)

// SMEM layout (floats):
//   h_s : [HID][TILE_B]          = 8192
//   W_s : [FEAT][G3]             = 10752
//   x_s : [FEAT][TILE_B]         = 1792
//   R_s : [KC][G3]               = 6144
#define SM_FLOATS (HID*TILE_B + FEAT*G3 + FEAT*TILE_B + KC*G3)
#define SM_BYTES  (SM_FLOATS * 4)

__device__ __forceinline__ float sigmoidf_(float v) {
    return 1.0f / (1.0f + __expf(-v));
}

__global__ __launch_bounds__(NTHREADS, 1)
void gru_fused_kernel(const float* __restrict__ x,      // (B,T,F,1)
                      const float* __restrict__ Wk,     // (F,3H)
                      const float* __restrict__ Rk,     // (H,3H)
                      const float* __restrict__ bias,   // (2,3H)
                      const float* __restrict__ dw,     // (H,C)
                      const float* __restrict__ db,     // (C)
                      float* __restrict__ out)          // (B,C)
{
    extern __shared__ float sm[];
    float* h_s = sm;                          // h_s[j*TILE_B + row], j = hidden col
    float* W_s = h_s + HID * TILE_B;          // W_s[k*G3 + c]
    float* x_s = W_s + FEAT * G3;             // x_s[f*TILE_B + row]
    float* R_s = x_s + FEAT * TILE_B;         // R_s[kk*G3 + c]

    const int tid = threadIdx.x;
    const int rg  = tid & 15;                 // 16 row groups * 4 rows = 64 rows
    const int cg  = tid >> 4;                 // 32 col groups * 4 cols = 128 h-cols
    const int r0  = rg * 4;
    const int j0  = cg * 4;
    const int b0  = blockIdx.x * TILE_B;

    // Load input-kernel W into SMEM (reused all 28 steps)
    for (int i = tid; i < FEAT * G3; i += NTHREADS) W_s[i] = Wk[i];
    // h0 = 0
    for (int i = tid; i < HID * TILE_B; i += NTHREADS) h_s[i] = 0.0f;

    // Per-thread gate biases (bias_i = bias[0..383], bias_r = bias[384..767])
    float bz[4], brg[4], bxh[4], brh[4];
#pragma unroll
    for (int c = 0; c < 4; c++) {
        bz[c]  = bias[j0 + c]            + bias[G3 + j0 + c];
        brg[c] = bias[HID + j0 + c]      + bias[G3 + HID + j0 + c];
        bxh[c] = bias[2*HID + j0 + c];
        brh[c] = bias[G3 + 2*HID + j0 + c];
    }

    __syncthreads();

    for (int t = 0; t < TSTEPS; t++) {
        // Stage x tile (transposed): x_s[f][row] = x[b0+row][t][f]
        for (int i = tid; i < FEAT * TILE_B; i += NTHREADS) {
            int row = i / FEAT;
            int f   = i % FEAT;
            x_s[f * TILE_B + row] =
                x[(size_t)(b0 + row) * (TSTEPS * FEAT) + t * FEAT + f];
        }
        __syncthreads();   // x_s ready; also orders prev-step h writes before h reads

        // Accumulators: z (x+rec fused), r (fused), rec-h, x-h
        float az[4][4], ar[4][4], ah[4][4], axh[4][4];
#pragma unroll
        for (int rr = 0; rr < 4; rr++)
#pragma unroll
            for (int c = 0; c < 4; c++) {
                az[rr][c] = 0.f; ar[rr][c] = 0.f;
                ah[rr][c] = 0.f; axh[rr][c] = 0.f;
            }

        // ---- Input projection: K = 28 over (x_s, W_s) ----
#pragma unroll 4
        for (int k = 0; k < FEAT; k++) {
            float4 a  = *(const float4*)&x_s[k * TILE_B + r0];
            float4 v0 = *(const float4*)&W_s[k * G3 + j0];
            float4 v1 = *(const float4*)&W_s[k * G3 + HID + j0];
            float4 v2 = *(const float4*)&W_s[k * G3 + 2*HID + j0];
            float av[4] = {a.x, a.y, a.z, a.w};
            float v0v[4] = {v0.x, v0.y, v0.z, v0.w};
            float v1v[4] = {v1.x, v1.y, v1.z, v1.w};
            float v2v[4] = {v2.x, v2.y, v2.z, v2.w};
#pragma unroll
            for (int rr = 0; rr < 4; rr++)
#pragma unroll
                for (int c = 0; c < 4; c++) {
                    az[rr][c]  = fmaf(av[rr], v0v[c], az[rr][c]);
                    ar[rr][c]  = fmaf(av[rr], v1v[c], ar[rr][c]);
                    axh[rr][c] = fmaf(av[rr], v2v[c], axh[rr][c]);
                }
        }

        // ---- Recurrent projection: K = 128 over (h_s, R streamed) ----
        for (int ch = 0; ch < HID / KC; ch++) {
            __syncthreads();   // previous chunk's compute done before R_s overwrite
            for (int i = tid; i < KC * G3; i += NTHREADS)
                R_s[i] = Rk[ch * KC * G3 + i];
            __syncthreads();
#pragma unroll 4
            for (int kk = 0; kk < KC; kk++) {
                int k = ch * KC + kk;
                float4 a  = *(const float4*)&h_s[k * TILE_B + r0];
                float4 v0 = *(const float4*)&R_s[kk * G3 + j0];
                float4 v1 = *(const float4*)&R_s[kk * G3 + HID + j0];
                float4 v2 = *(const float4*)&R_s[kk * G3 + 2*HID + j0];
                float av[4] = {a.x, a.y, a.z, a.w};
                float v0v[4] = {v0.x, v0.y, v0.z, v0.w};
                float v1v[4] = {v1.x, v1.y, v1.z, v1.w};
                float v2v[4] = {v2.x, v2.y, v2.z, v2.w};
#pragma unroll
                for (int rr = 0; rr < 4; rr++)
#pragma unroll
                    for (int c = 0; c < 4; c++) {
                        az[rr][c] = fmaf(av[rr], v0v[c], az[rr][c]);
                        ar[rr][c] = fmaf(av[rr], v1v[c], ar[rr][c]);
                        ah[rr][c] = fmaf(av[rr], v2v[c], ah[rr][c]);
                    }
            }
        }

        // ---- Gates + state update ----
        float hn[4][4];
#pragma unroll
        for (int c = 0; c < 4; c++) {
            float4 hv = *(const float4*)&h_s[(j0 + c) * TILE_B + r0];
            float ho[4] = {hv.x, hv.y, hv.z, hv.w};
#pragma unroll
            for (int rr = 0; rr < 4; rr++) {
                float z  = sigmoidf_(az[rr][c] + bz[c]);
                float r  = sigmoidf_(ar[rr][c] + brg[c]);
                float hh = tanhf(axh[rr][c] + bxh[c] + r * (ah[rr][c] + brh[c]));
                hn[rr][c] = z * ho[rr] + (1.0f - z) * hh;
            }
        }

        __syncthreads();   // all h_s reads complete before overwrite
#pragma unroll
        for (int c = 0; c < 4; c++) {
            float4 v = make_float4(hn[0][c], hn[1][c], hn[2][c], hn[3][c]);
            *(float4*)&h_s[(j0 + c) * TILE_B + r0] = v;
        }
        // next iteration's x-ready sync orders these writes before the next reads
    }

    __syncthreads();

    // ---- Dense + softmax epilogue (h resident in SMEM) ----
    if (tid < TILE_B) {
        const int row = tid;
        float lg[NCLS];
#pragma unroll
        for (int c = 0; c < NCLS; c++) lg[c] = db[c];
        for (int j = 0; j < HID; j++) {
            float hv = h_s[j * TILE_B + row];
#pragma unroll
            for (int c = 0; c < NCLS; c++)
                lg[c] = fmaf(hv, dw[j * NCLS + c], lg[c]);
        }
        float m = lg[0];
#pragma unroll
        for (int c = 1; c < NCLS; c++) m = fmaxf(m, lg[c]);
        float s = 0.0f;
#pragma unroll
        for (int c = 0; c < NCLS; c++) { lg[c] = expf(lg[c] - m); s += lg[c]; }
        float inv = 1.0f / s;
#pragma unroll
        for (int c = 0; c < NCLS; c++)
            out[(size_t)(b0 + row) * NCLS + c] = lg[c] * inv;
    }
}

extern "C" void kernel_launch(void* const* d_in, const int* in_sizes, int n_in,
                              void* d_out, int out_size) {
    const float* x    = (const float*)d_in[0];
    const float* Wk   = (const float*)d_in[1];
    const float* Rk   = (const float*)d_in[2];
    const float* bias = (const float*)d_in[3];
    const float* dw   = (const float*)d_in[4];
    const float* db   = (const float*)d_in[5];
    float* out = (float*)d_out;

    cudaFuncSetAttribute(gru_fused_kernel,
                         cudaFuncAttributeMaxDynamicSharedMemorySize, SM_BYTES);

    gru_fused_kernel<<<BATCH / TILE_B, NTHREADS, SM_BYTES>>>(
        x, Wk, Rk, bias, dw, db, out);
}

// round 3
// speedup vs baseline: 1.2341x; 1.2327x over previous
#include <cuda_runtime.h>
#include <math.h>

// Problem constants
#define BATCH   16384
#define TSTEPS  28
#define FEAT    28
#define HID     128
#define G3      384     // 3*HID
#define NCLS    10

#define TILE_B  64
#define NTHREADS 512
#define KC      16      // R streaming chunk (rows of k)

// SMEM layout (floats):
//   h_s : [HID][TILE_B]          = 8192
//   W_s : [FEAT][G3]             = 10752
//   x_s : [FEAT][TILE_B]         = 1792
//   R_s : 2 x [KC][G3]           = 12288 (double buffered)
#define SM_FLOATS (HID*TILE_B + FEAT*G3 + FEAT*TILE_B + 2*KC*G3)
#define SM_BYTES  (SM_FLOATS * 4)

typedef unsigned long long u64;

__device__ __forceinline__ float sigmoidf_(float v) {
    return 1.0f / (1.0f + __expf(-v));
}

// packed dual-fp32 FMA: d = a * b + d   (Blackwell f32x2 path, 2 FLOPs/slot*2)
__device__ __forceinline__ void fma2(u64& d, u64 a, u64 b) {
    asm("fma.rn.f32x2 %0, %1, %2, %0;" : "+l"(d) : "l"(a), "l"(b));
}

// broadcast one fp32 into both halves of a 64-bit packed register
__device__ __forceinline__ u64 bcast2(float v) {
    u64 r;
    asm("mov.b64 %0, {%1, %1};" : "=l"(r) : "f"(v));
    return r;
}

__device__ __forceinline__ float2 unpack2(u64 v) {
    float2 r;
    asm("mov.b64 {%0, %1}, %2;" : "=f"(r.x), "=f"(r.y) : "l"(v));
    return r;
}

__global__ __launch_bounds__(NTHREADS, 1)
void gru_fused_kernel(const float* __restrict__ x,      // (B,T,F,1)
                      const float* __restrict__ Wk,     // (F,3H)
                      const float* __restrict__ Rk,     // (H,3H)
                      const float* __restrict__ bias,   // (2,3H)
                      const float* __restrict__ dw,     // (H,C)
                      const float* __restrict__ db,     // (C)
                      float* __restrict__ out)          // (B,C)
{
    extern __shared__ float sm[];
    float* h_s = sm;                          // h_s[j*TILE_B + row]
    float* W_s = h_s + HID * TILE_B;          // W_s[k*G3 + c]
    float* x_s = W_s + FEAT * G3;             // x_s[f*TILE_B + row]
    float* R_s = x_s + FEAT * TILE_B;         // 2 buffers of [KC][G3]

    const int tid = threadIdx.x;
    const int rg  = tid & 15;                 // 16 row groups * 4 rows = 64 rows
    const int cg  = tid >> 4;                 // 32 col groups * 4 cols = 128 h-cols
    const int r0  = rg * 4;
    const int j0  = cg * 4;
    const int b0  = blockIdx.x * TILE_B;

    for (int i = tid; i < FEAT * G3; i += NTHREADS) W_s[i] = Wk[i];
    for (int i = tid; i < HID * TILE_B; i += NTHREADS) h_s[i] = 0.0f;

    // Per-thread gate biases for cols j0..j0+3
    float bz[4], brg[4], bxh[4], brh[4];
#pragma unroll
    for (int c = 0; c < 4; c++) {
        bz[c]  = bias[j0 + c]            + bias[G3 + j0 + c];
        brg[c] = bias[HID + j0 + c]      + bias[G3 + HID + j0 + c];
        bxh[c] = bias[2*HID + j0 + c];
        brh[c] = bias[G3 + 2*HID + j0 + c];
    }

    __syncthreads();

    for (int t = 0; t < TSTEPS; t++) {
        // Stage x tile (transposed): x_s[f][row] = x[b0+row][t][f]
        for (int i = tid; i < FEAT * TILE_B; i += NTHREADS) {
            int row = i / FEAT;
            int f   = i % FEAT;
            x_s[f * TILE_B + row] =
                x[(size_t)(b0 + row) * (TSTEPS * FEAT) + t * FEAT + f];
        }
        // Stage R chunk 0 into buffer 0
        for (int i = tid; i < KC * G3; i += NTHREADS) R_s[i] = Rk[i];
        __syncthreads();   // x_s + R chunk0 ready; prev-step h writes ordered

        // Accumulators: [4 rows][2 col-pairs], packed fp32x2 across adjacent cols
        u64 az[4][2], ar[4][2], ah[4][2], axh[4][2];
#pragma unroll
        for (int rr = 0; rr < 4; rr++)
#pragma unroll
            for (int p = 0; p < 2; p++) {
                az[rr][p] = 0ull; ar[rr][p] = 0ull;
                ah[rr][p] = 0ull; axh[rr][p] = 0ull;
            }

        // ---- Input projection: K = 28 over (x_s, W_s) ----
#pragma unroll 4
        for (int k = 0; k < FEAT; k++) {
            float4 af = *(const float4*)&x_s[k * TILE_B + r0];
            u64 a[4] = {bcast2(af.x), bcast2(af.y), bcast2(af.z), bcast2(af.w)};
            ulonglong2 v0 = *(const ulonglong2*)&W_s[k * G3 + j0];
            ulonglong2 v1 = *(const ulonglong2*)&W_s[k * G3 + HID + j0];
            ulonglong2 v2 = *(const ulonglong2*)&W_s[k * G3 + 2*HID + j0];
#pragma unroll
            for (int rr = 0; rr < 4; rr++) {
                fma2(az[rr][0],  a[rr], v0.x); fma2(az[rr][1],  a[rr], v0.y);
                fma2(ar[rr][0],  a[rr], v1.x); fma2(ar[rr][1],  a[rr], v1.y);
                fma2(axh[rr][0], a[rr], v2.x); fma2(axh[rr][1], a[rr], v2.y);
            }
        }

        // ---- Recurrent projection: K = 128, R double-buffered in SMEM ----
        for (int ch = 0; ch < HID / KC; ch++) {
            float* cur = R_s + (ch & 1) * (KC * G3);
            float* nxt = R_s + ((ch + 1) & 1) * (KC * G3);

            // Prefetch next chunk into registers (latency hidden by compute)
            float4 pr0, pr1, pr2;
            if (ch < HID / KC - 1) {
                const float* src = Rk + (ch + 1) * KC * G3;
                pr0 = *(const float4*)&src[0 * 2048 + tid * 4];
                pr1 = *(const float4*)&src[1 * 2048 + tid * 4];
                pr2 = *(const float4*)&src[2 * 2048 + tid * 4];
            }

#pragma unroll 4
            for (int kk = 0; kk < KC; kk++) {
                int k = ch * KC + kk;
                float4 af = *(const float4*)&h_s[k * TILE_B + r0];
                u64 a[4] = {bcast2(af.x), bcast2(af.y), bcast2(af.z), bcast2(af.w)};
                ulonglong2 v0 = *(const ulonglong2*)&cur[kk * G3 + j0];
                ulonglong2 v1 = *(const ulonglong2*)&cur[kk * G3 + HID + j0];
                ulonglong2 v2 = *(const ulonglong2*)&cur[kk * G3 + 2*HID + j0];
#pragma unroll
                for (int rr = 0; rr < 4; rr++) {
                    fma2(az[rr][0], a[rr], v0.x); fma2(az[rr][1], a[rr], v0.y);
                    fma2(ar[rr][0], a[rr], v1.x); fma2(ar[rr][1], a[rr], v1.y);
                    fma2(ah[rr][0], a[rr], v2.x); fma2(ah[rr][1], a[rr], v2.y);
                }
            }

            if (ch < HID / KC - 1) {
                *(float4*)&nxt[0 * 2048 + tid * 4] = pr0;
                *(float4*)&nxt[1 * 2048 + tid * 4] = pr1;
                *(float4*)&nxt[2 * 2048 + tid * 4] = pr2;
            }
            __syncthreads();   // publish next buffer / guard current buffer reuse
        }

        // ---- Gates + state update (after final chunk barrier: all h reads done) ----
        float hn[4][4];
#pragma unroll
        for (int p = 0; p < 2; p++) {
#pragma unroll
            for (int rr = 0; rr < 4; rr++) {
                float2 z2  = unpack2(az[rr][p]);
                float2 r2  = unpack2(ar[rr][p]);
                float2 h2  = unpack2(ah[rr][p]);
                float2 xh2 = unpack2(axh[rr][p]);
                int c0 = 2 * p, c1 = 2 * p + 1;
                {
                    float z  = sigmoidf_(z2.x + bz[c0]);
                    float r  = sigmoidf_(r2.x + brg[c0]);
                    float hh = tanhf(xh2.x + bxh[c0] + r * (h2.x + brh[c0]));
                    float ho = h_s[(j0 + c0) * TILE_B + r0 + rr];
                    hn[rr][c0] = z * ho + (1.0f - z) * hh;
                }
                {
                    float z  = sigmoidf_(z2.y + bz[c1]);
                    float r  = sigmoidf_(r2.y + brg[c1]);
                    float hh = tanhf(xh2.y + bxh[c1] + r * (h2.y + brh[c1]));
                    float ho = h_s[(j0 + c1) * TILE_B + r0 + rr];
                    hn[rr][c1] = z * ho + (1.0f - z) * hh;
                }
            }
        }

        // h_s[(j0+c)][r0..r0+3] has a unique owner (this thread) for both the
        // ho reads above and these writes; cross-thread reads of h_s were all
        // matmul reads, ordered by the final chunk barrier.
#pragma unroll
        for (int c = 0; c < 4; c++) {
            float4 v = make_float4(hn[0][c], hn[1][c], hn[2][c], hn[3][c]);
            *(float4*)&h_s[(j0 + c) * TILE_B + r0] = v;
        }
        __syncthreads();   // h writes visible before next step's matmul reads
    }

    // ---- Dense + softmax epilogue (h resident in SMEM) ----
    if (tid < TILE_B) {
        const int row = tid;
        float lg[NCLS];
#pragma unroll
        for (int c = 0; c < NCLS; c++) lg[c] = db[c];
        for (int j = 0; j < HID; j++) {
            float hv = h_s[j * TILE_B + row];
#pragma unroll
            for (int c = 0; c < NCLS; c++)
                lg[c] = fmaf(hv, dw[j * NCLS + c], lg[c]);
        }
        float m = lg[0];
#pragma unroll
        for (int c = 1; c < NCLS; c++) m = fmaxf(m, lg[c]);
        float s = 0.0f;
#pragma unroll
        for (int c = 0; c < NCLS; c++) { lg[c] = expf(lg[c] - m); s += lg[c]; }
        float inv = 1.0f / s;
#pragma unroll
        for (int c = 0; c < NCLS; c++)
            out[(size_t)(b0 + row) * NCLS + c] = lg[c] * inv;
    }
}

extern "C" void kernel_launch(void* const* d_in, const int* in_sizes, int n_in,
                              void* d_out, int out_size) {
    const float* x    = (const float*)d_in[0];
    const float* Wk   = (const float*)d_in[1];
    const float* Rk   = (const float*)d_in[2];
    const float* bias = (const float*)d_in[3];
    const float* dw   = (const float*)d_in[4];
    const float* db   = (const float*)d_in[5];
    float* out = (float*)d_out;

    cudaFuncSetAttribute(gru_fused_kernel,
                         cudaFuncAttributeMaxDynamicSharedMemorySize, SM_BYTES);

    gru_fused_kernel<<<BATCH / TILE_B, NTHREADS, SM_BYTES>>>(
        x, Wk, Rk, bias, dw, db, out);
}